// round 13
// baseline (speedup 1.0000x reference)
#include <cuda_runtime.h>

#define B_ 32
#define M_ 2048
#define H_ 1024
#define NTOK (B_*M_)
#define THRESH 0.99f
#define BLOCKS_PER_BATCH (M_/4)   // 4 tokens per block -> 512 main blocks/batch
#define GROUPS (B_+2)             // pipeline: pack(b) rides in group b+2

// Scratch (no allocations allowed).
__device__ int g_rank[NTOK];          // clip(cumsum(run)-1, 0, M-1)
__device__ unsigned char g_runb[NTOK];// decoded run mask
__device__ int g_src[NTOK];           // run_new ? rank : -1
__device__ int g_gidx[NTOK];          // packed row d -> source row in h, -1 => zero row
__device__ int g_done[B_];            // per-batch completion counters
__device__ int g_ready[B_];           // per-batch "gidx compacted" flags

// ---------------------------------------------------------------------------
// K0: wire-format probe + decode + per-batch rank scan. Resets g_done/g_ready.
// Both format interpretations loaded before the probe resolves.
// ---------------------------------------------------------------------------
__global__ void rank_kernel(const void* __restrict__ run) {
    const int b = blockIdx.x;
    const int t = threadIdx.x;            // 256 threads
    const unsigned int* w = (const unsigned int*)run;

    if (t == 0) { g_done[b] = 0; g_ready[b] = 0; }

    unsigned int p0 = w[b * 512 + t];
    unsigned int p1 = w[b * 512 + 256 + t];
    const int base = t * 8;
    uint2 u8v = *(const uint2*)((const unsigned char*)run + b * M_ + base);
    int4 i0 = ((const int4*)((const int*)run + b * M_ + base))[0];
    int4 i1 = ((const int4*)((const int*)run + b * M_ + base))[1];

    int found = ((p0 | p1) & 0xFFFFFF00u) ? 1 : 0;
    const int fmt_u8 = __syncthreads_or(found);

    int v[8];
    if (fmt_u8) {
        v[0] = (u8v.x & 0x000000FFu) != 0; v[1] = (u8v.x & 0x0000FF00u) != 0;
        v[2] = (u8v.x & 0x00FF0000u) != 0; v[3] = (u8v.x & 0xFF000000u) != 0;
        v[4] = (u8v.y & 0x000000FFu) != 0; v[5] = (u8v.y & 0x0000FF00u) != 0;
        v[6] = (u8v.y & 0x00FF0000u) != 0; v[7] = (u8v.y & 0xFF000000u) != 0;
    } else {
        v[0] = i0.x != 0; v[1] = i0.y != 0; v[2] = i0.z != 0; v[3] = i0.w != 0;
        v[4] = i1.x != 0; v[5] = i1.y != 0; v[6] = i1.z != 0; v[7] = i1.w != 0;
    }
    int s = 0;
    #pragma unroll
    for (int i = 0; i < 8; i++) {
        s += v[i];
        g_runb[b * M_ + base + i] = (unsigned char)v[i];
    }

    const int lane = t & 31, warp = t >> 5;
    int x = s;
    #pragma unroll
    for (int o = 1; o < 32; o <<= 1) {
        int y = __shfl_up_sync(0xffffffffu, x, o);
        if (lane >= o) x += y;
    }
    __shared__ int wsum[8], woff[8];
    if (lane == 31) wsum[warp] = x;
    __syncthreads();
    if (t == 0) { int a = 0; for (int i = 0; i < 8; i++) { woff[i] = a; a += wsum[i]; } }
    __syncthreads();

    int c = woff[warp] + (x - s);
    #pragma unroll
    for (int i = 0; i < 8; i++) {
        c += v[i];
        int rk = c - 1;
        if (rk < 0) rk = 0;
        g_rank[b * M_ + base + i] = rk;
    }
}

// ---------------------------------------------------------------------------
// K1: fused main + dispatch-interleaved pack.
// blockIdx -> (group, slot): slot<512 = main block for batch `group`;
// slot>=512 = pack block for batch `group-2`. Dispatch order thus interleaves
// pack(b) between main(b+2) and main(b+3), overlapping pack's write-only
// stream with main's read-heavy stream and reusing L2-hot h rows.
// With offset 2048+ vids > resident window (~1300 blocks), main(b) has
// retired before pack(b) becomes resident -> the g_ready spin is ~never
// taken (kept only as a hard correctness gate; main blocks never wait, so
// no deadlock is possible). The R11 lesson (no waiting while holding SM
// slots mid-stream) is preserved.
// ---------------------------------------------------------------------------
__global__ __launch_bounds__(128) void fused_kernel(
    const float* __restrict__ h, const float* __restrict__ W,
    const float* __restrict__ bias, const float* __restrict__ wh,
    const float* __restrict__ accp,
    float* __restrict__ packed, float* __restrict__ weighted_out,
    float* __restrict__ acc_out)
{
    __shared__ float sW[H_];
    __shared__ float sWH[4 * H_];      // 4 token rows of weighted_h

    const int group = blockIdx.x >> 10;
    const int slot  = blockIdx.x & 1023;
    const int warp = threadIdx.x >> 5, lane = threadIdx.x & 31;

    if (slot >= 512) {
        // ================= pack path: batch = group - 2 =================
        if (group < 2) return;
        const int b = group - 2;
        const int tok = b * M_ + (slot - 512) * 4 + warp;

        cudaGridDependencySynchronize();   // rank_kernel reset of g_ready visible
        if (threadIdx.x == 0) {
            while (*(volatile int*)&g_ready[b] == 0) __nanosleep(128);
            __threadfence();               // acquire: order g_gidx reads after flag
        }
        __syncthreads();

        const int g = g_gidx[tok];
        float4* out = (float4*)(packed + (size_t)tok * H_);
        if (g >= 0) {
            const float4* hrow = (const float4*)(h + ((size_t)b * M_ + g) * H_);
            float4 r[8];
            #pragma unroll
            for (int i = 0; i < 8; i++) r[i] = hrow[lane + i * 32];  // L2-hot
            #pragma unroll
            for (int i = 0; i < 8; i++) out[lane + i * 32] = r[i];
        } else {
            const float4 z = make_float4(0.f, 0.f, 0.f, 0.f);
            #pragma unroll
            for (int i = 0; i < 8; i++) out[lane + i * 32] = z;
        }
        return;
    }

    // ================= main path: batch = group =================
    if (group >= B_) return;               // groups 32,33 have no main half
    const int b = group;
    const int tok = b * M_ + slot * 4 + warp;

    // ---- rank-independent prefetch (overlaps rank_kernel via PDL) ----
    for (int i = threadIdx.x; i < H_ / 4; i += 128)
        ((float4*)sW)[i] = ((const float4*)W)[i];

    {   // stage this warp's wh row: 8x LDG.128 -> 8x STS.128
        const float4* whrow = (const float4*)(wh + (size_t)tok * H_);
        float4* swh = (float4*)(sWH + warp * H_);
        float4 r[8];
        #pragma unroll
        for (int i = 0; i < 8; i++) r[i] = whrow[lane + i * 32];
        #pragma unroll
        for (int i = 0; i < 8; i++) swh[lane + i * 32] = r[i];
    }
    float acc = accp[tok];
    const float bv = bias[0];

    cudaGridDependencySynchronize();   // rank_kernel outputs now visible
    __syncthreads();

    const bool running = g_runb[tok] != 0;
    const int rank = g_rank[tok];

    float4 hv[8];
    float dot = 0.0f;
    if (running) {
        const float4* hrow = (const float4*)(h + ((size_t)b * M_ + rank) * H_);
        #pragma unroll
        for (int i = 0; i < 8; i++) {
            float4 a = hrow[lane + i * 32];
            hv[i] = a;
            float4 wv = ((const float4*)sW)[lane + i * 32];
            dot += a.x * wv.x;
            dot += a.y * wv.y;
            dot += a.z * wv.z;
            dot += a.w * wv.w;
        }
    } else {
        #pragma unroll
        for (int i = 0; i < 8; i++) hv[i] = make_float4(0.f, 0.f, 0.f, 0.f);
    }
    #pragma unroll
    for (int o = 16; o > 0; o >>= 1)
        dot += __shfl_xor_sync(0xffffffffu, dot, o);

    float p_adj = 0.0f;
    bool run_new = false;
    if (running) {
        float z = dot + bv;
        float p = 1.0f / (1.0f + expf(-z));
        float acc_new = acc + p;
        run_new = acc_new < THRESH;
        p_adj = run_new ? p : (1.0f - (acc_new - p));
        acc = acc_new;
    }
    if (lane == 0) {
        acc_out[tok] = acc;
        g_src[tok] = run_new ? rank : -1;
    }

    float4* wo = (float4*)(weighted_out + (size_t)tok * H_);
    const float4* swh = (const float4*)(sWH + warp * H_);
    const float q = 1.0f - p_adj;
    #pragma unroll
    for (int i = 0; i < 8; i++) {
        float4 w4 = swh[lane + i * 32];
        float4 o4;
        o4.x = hv[i].x * p_adj + w4.x * q;
        o4.y = hv[i].y * p_adj + w4.y * q;
        o4.z = hv[i].z * p_adj + w4.z * q;
        o4.w = hv[i].w * p_adj + w4.w * q;
        wo[lane + i * 32] = o4;
    }

    // ---- fused per-batch compaction: last-arriving block does the scan ----
    __shared__ int s_last;
    __syncthreads();                 // all warps' g_src writes issued
    if (threadIdx.x == 0) {
        __threadfence();             // release g_src to other SMs
        int n = atomicAdd(&g_done[b], 1);
        s_last = (n == BLOCKS_PER_BATCH - 1);
    }
    __syncthreads();
    if (!s_last) return;

    const int t = threadIdx.x;
    const int base = b * M_ + t * 16;
    int src[16], v[16];
    int s = 0;
    #pragma unroll
    for (int i = 0; i < 16; i++) {
        src[i] = g_src[base + i];
        v[i] = (src[i] >= 0) ? 1 : 0;
        s += v[i];
        g_gidx[base + i] = -1;       // default: zero row
    }
    int x = s;
    #pragma unroll
    for (int o = 1; o < 32; o <<= 1) {
        int y = __shfl_up_sync(0xffffffffu, x, o);
        if (lane >= o) x += y;
    }
    __shared__ int cw[4], co[4];
    if (lane == 31) cw[warp] = x;
    __syncthreads();
    if (t == 0) { int a = 0; for (int i = 0; i < 4; i++) { co[i] = a; a += cw[i]; } }
    __syncthreads();                 // orders the -1 init before scatter

    int pos = co[warp] + (x - s);
    #pragma unroll
    for (int i = 0; i < 16; i++) {
        if (v[i]) {
            g_gidx[b * M_ + pos] = src[i];
            pos++;
        }
    }
    if (t == 0) {
        __threadfence();             // release g_gidx
        *(volatile int*)&g_ready[b] = 1;
    }
}

// ---------------------------------------------------------------------------
extern "C" void kernel_launch(void* const* d_in, const int* in_sizes, int n_in,
                              void* d_out, int out_size) {
    const float* h    = (const float*)d_in[0];
    const float* W    = (const float*)d_in[1];
    const float* bias = (const float*)d_in[2];
    const float* wh   = (const float*)d_in[3];
    const float* accp = (const float*)d_in[4];
    const void*  run  = d_in[5];

    float* out      = (float*)d_out;
    float* packed   = out;                              // [B,M,H]
    float* weighted = out + (size_t)NTOK * H_;          // [B,M,H]
    float* acc      = out + 2 * (size_t)NTOK * H_;      // [B,M,1]

    rank_kernel<<<B_, 256>>>(run);

    cudaLaunchAttribute attr[1];
    attr[0].id = cudaLaunchAttributeProgrammaticStreamSerialization;
    attr[0].val.programmaticStreamSerializationAllowed = 1;

    cudaLaunchConfig_t cfg = {};
    cfg.gridDim = dim3(GROUPS * 1024);
    cfg.blockDim = dim3(128);
    cfg.dynamicSmemBytes = 0;
    cfg.stream = 0;
    cfg.attrs = attr;
    cfg.numAttrs = 1;
    cudaLaunchKernelEx(&cfg, fused_kernel, h, W, bias, wh, accp,
                       packed, weighted, acc);
}

// round 14
// speedup vs baseline: 1.3247x; 1.3247x over previous
#include <cuda_runtime.h>

#define B_ 32
#define M_ 2048
#define H_ 1024
#define NTOK (B_*M_)
#define THRESH 0.99f
#define BLOCKS_PER_BATCH (M_/4)   // 4 tokens per block -> 512 main blocks/batch
#define PIPE_OFF 4                // pack(b) rides in group b+PIPE_OFF
#define GROUPS (B_+PIPE_OFF)

// Scratch (no allocations allowed).
__device__ int g_rank[NTOK];          // clip(cumsum(run)-1, 0, M-1)
__device__ unsigned char g_runb[NTOK];// decoded run mask
__device__ int g_src[NTOK];           // run_new ? rank : -1
__device__ int g_gidx[NTOK];          // packed row d -> source row in h, -1 => zero row
__device__ int g_done[B_];            // per-batch completion counters
__device__ int g_ready[B_];           // per-batch "gidx compacted" flags

// ---------------------------------------------------------------------------
// K0: wire-format probe + decode + per-batch rank scan. Resets g_done/g_ready.
// Both format interpretations loaded before the probe resolves.
// ---------------------------------------------------------------------------
__global__ void rank_kernel(const void* __restrict__ run) {
    const int b = blockIdx.x;
    const int t = threadIdx.x;            // 256 threads
    const unsigned int* w = (const unsigned int*)run;

    if (t == 0) { g_done[b] = 0; g_ready[b] = 0; }

    unsigned int p0 = w[b * 512 + t];
    unsigned int p1 = w[b * 512 + 256 + t];
    const int base = t * 8;
    uint2 u8v = *(const uint2*)((const unsigned char*)run + b * M_ + base);
    int4 i0 = ((const int4*)((const int*)run + b * M_ + base))[0];
    int4 i1 = ((const int4*)((const int*)run + b * M_ + base))[1];

    int found = ((p0 | p1) & 0xFFFFFF00u) ? 1 : 0;
    const int fmt_u8 = __syncthreads_or(found);

    int v[8];
    if (fmt_u8) {
        v[0] = (u8v.x & 0x000000FFu) != 0; v[1] = (u8v.x & 0x0000FF00u) != 0;
        v[2] = (u8v.x & 0x00FF0000u) != 0; v[3] = (u8v.x & 0xFF000000u) != 0;
        v[4] = (u8v.y & 0x000000FFu) != 0; v[5] = (u8v.y & 0x0000FF00u) != 0;
        v[6] = (u8v.y & 0x00FF0000u) != 0; v[7] = (u8v.y & 0xFF000000u) != 0;
    } else {
        v[0] = i0.x != 0; v[1] = i0.y != 0; v[2] = i0.z != 0; v[3] = i0.w != 0;
        v[4] = i1.x != 0; v[5] = i1.y != 0; v[6] = i1.z != 0; v[7] = i1.w != 0;
    }
    int s = 0;
    #pragma unroll
    for (int i = 0; i < 8; i++) {
        s += v[i];
        g_runb[b * M_ + base + i] = (unsigned char)v[i];
    }

    const int lane = t & 31, warp = t >> 5;
    int x = s;
    #pragma unroll
    for (int o = 1; o < 32; o <<= 1) {
        int y = __shfl_up_sync(0xffffffffu, x, o);
        if (lane >= o) x += y;
    }
    __shared__ int wsum[8], woff[8];
    if (lane == 31) wsum[warp] = x;
    __syncthreads();
    if (t == 0) { int a = 0; for (int i = 0; i < 8; i++) { woff[i] = a; a += wsum[i]; } }
    __syncthreads();

    int c = woff[warp] + (x - s);
    #pragma unroll
    for (int i = 0; i < 8; i++) {
        c += v[i];
        int rk = c - 1;
        if (rk < 0) rk = 0;
        g_rank[b * M_ + base + i] = rk;
    }
}

// ---------------------------------------------------------------------------
// K1: fused main + dispatch-interleaved pack, pipeline offset = 4 batches.
// blockIdx -> (group, slot): slot<512 = main block for batch `group`;
// slot>=512 = pack block for batch `group-4`. The 4-batch offset (4097 vids,
// ~2.8x the ~1480-block resident window) guarantees main(b) AND its
// compactor have retired long before pack(b) becomes resident, so the
// g_ready gate never actually spins (kept as a hard correctness fence; main
// blocks never wait -> deadlock impossible). Pack's write-only stream now
// interleaves with main's read-heavy stream, and pack's h gathers hit a
// recent L2 window instead of a 500MB-stale one.
// ---------------------------------------------------------------------------
__global__ __launch_bounds__(128) void fused_kernel(
    const float* __restrict__ h, const float* __restrict__ W,
    const float* __restrict__ bias, const float* __restrict__ wh,
    const float* __restrict__ accp,
    float* __restrict__ packed, float* __restrict__ weighted_out,
    float* __restrict__ acc_out)
{
    __shared__ float sW[H_];
    __shared__ float sWH[4 * H_];      // 4 token rows of weighted_h

    const int group = blockIdx.x >> 10;
    const int slot  = blockIdx.x & 1023;
    const int warp = threadIdx.x >> 5, lane = threadIdx.x & 31;

    if (slot >= 512) {
        // ================= pack path: batch = group - PIPE_OFF =================
        if (group < PIPE_OFF) return;
        const int b = group - PIPE_OFF;
        const int tok = b * M_ + (slot - 512) * 4 + warp;

        cudaGridDependencySynchronize();   // rank_kernel reset of g_ready visible
        if (threadIdx.x == 0) {
            while (*(volatile int*)&g_ready[b] == 0) __nanosleep(128);
            __threadfence();               // acquire: order g_gidx reads after flag
        }
        __syncthreads();

        const int g = g_gidx[tok];
        float4* out = (float4*)(packed + (size_t)tok * H_);
        if (g >= 0) {
            const float4* hrow = (const float4*)(h + ((size_t)b * M_ + g) * H_);
            float4 r[8];
            #pragma unroll
            for (int i = 0; i < 8; i++) r[i] = hrow[lane + i * 32];  // L2-recent
            #pragma unroll
            for (int i = 0; i < 8; i++) out[lane + i * 32] = r[i];
        } else {
            const float4 z = make_float4(0.f, 0.f, 0.f, 0.f);
            #pragma unroll
            for (int i = 0; i < 8; i++) out[lane + i * 32] = z;
        }
        return;
    }

    // ================= main path: batch = group =================
    if (group >= B_) return;               // trailing groups have no main half
    const int b = group;
    const int tok = b * M_ + slot * 4 + warp;

    // ---- rank-independent prefetch (overlaps rank_kernel via PDL) ----
    for (int i = threadIdx.x; i < H_ / 4; i += 128)
        ((float4*)sW)[i] = ((const float4*)W)[i];

    {   // stage this warp's wh row: 8x LDG.128 -> 8x STS.128
        const float4* whrow = (const float4*)(wh + (size_t)tok * H_);
        float4* swh = (float4*)(sWH + warp * H_);
        float4 r[8];
        #pragma unroll
        for (int i = 0; i < 8; i++) r[i] = whrow[lane + i * 32];
        #pragma unroll
        for (int i = 0; i < 8; i++) swh[lane + i * 32] = r[i];
    }
    float acc = accp[tok];
    const float bv = bias[0];

    cudaGridDependencySynchronize();   // rank_kernel outputs now visible
    __syncthreads();

    const bool running = g_runb[tok] != 0;
    const int rank = g_rank[tok];

    float4 hv[8];
    float dot = 0.0f;
    if (running) {
        const float4* hrow = (const float4*)(h + ((size_t)b * M_ + rank) * H_);
        #pragma unroll
        for (int i = 0; i < 8; i++) {
            float4 a = hrow[lane + i * 32];
            hv[i] = a;
            float4 wv = ((const float4*)sW)[lane + i * 32];
            dot += a.x * wv.x;
            dot += a.y * wv.y;
            dot += a.z * wv.z;
            dot += a.w * wv.w;
        }
    } else {
        #pragma unroll
        for (int i = 0; i < 8; i++) hv[i] = make_float4(0.f, 0.f, 0.f, 0.f);
    }
    #pragma unroll
    for (int o = 16; o > 0; o >>= 1)
        dot += __shfl_xor_sync(0xffffffffu, dot, o);

    float p_adj = 0.0f;
    bool run_new = false;
    if (running) {
        float z = dot + bv;
        float p = 1.0f / (1.0f + expf(-z));
        float acc_new = acc + p;
        run_new = acc_new < THRESH;
        p_adj = run_new ? p : (1.0f - (acc_new - p));
        acc = acc_new;
    }
    if (lane == 0) {
        acc_out[tok] = acc;
        g_src[tok] = run_new ? rank : -1;
    }

    float4* wo = (float4*)(weighted_out + (size_t)tok * H_);
    const float4* swh = (const float4*)(sWH + warp * H_);
    const float q = 1.0f - p_adj;
    #pragma unroll
    for (int i = 0; i < 8; i++) {
        float4 w4 = swh[lane + i * 32];
        float4 o4;
        o4.x = hv[i].x * p_adj + w4.x * q;
        o4.y = hv[i].y * p_adj + w4.y * q;
        o4.z = hv[i].z * p_adj + w4.z * q;
        o4.w = hv[i].w * p_adj + w4.w * q;
        wo[lane + i * 32] = o4;
    }

    // ---- fused per-batch compaction: last-arriving block does the scan ----
    __shared__ int s_last;
    __syncthreads();                 // all warps' g_src writes issued
    if (threadIdx.x == 0) {
        __threadfence();             // release g_src to other SMs
        int n = atomicAdd(&g_done[b], 1);
        s_last = (n == BLOCKS_PER_BATCH - 1);
    }
    __syncthreads();
    if (!s_last) return;

    const int t = threadIdx.x;
    const int base = b * M_ + t * 16;
    int src[16], v[16];
    int s = 0;
    #pragma unroll
    for (int i = 0; i < 16; i++) {
        src[i] = g_src[base + i];
        v[i] = (src[i] >= 0) ? 1 : 0;
        s += v[i];
        g_gidx[base + i] = -1;       // default: zero row
    }
    int x = s;
    #pragma unroll
    for (int o = 1; o < 32; o <<= 1) {
        int y = __shfl_up_sync(0xffffffffu, x, o);
        if (lane >= o) x += y;
    }
    __shared__ int cw[4], co[4];
    if (lane == 31) cw[warp] = x;
    __syncthreads();
    if (t == 0) { int a = 0; for (int i = 0; i < 4; i++) { co[i] = a; a += cw[i]; } }
    __syncthreads();                 // orders the -1 init before scatter

    int pos = co[warp] + (x - s);
    #pragma unroll
    for (int i = 0; i < 16; i++) {
        if (v[i]) {
            g_gidx[b * M_ + pos] = src[i];
            pos++;
        }
    }
    if (t == 0) {
        __threadfence();             // release g_gidx
        *(volatile int*)&g_ready[b] = 1;
    }
}

// ---------------------------------------------------------------------------
extern "C" void kernel_launch(void* const* d_in, const int* in_sizes, int n_in,
                              void* d_out, int out_size) {
    const float* h    = (const float*)d_in[0];
    const float* W    = (const float*)d_in[1];
    const float* bias = (const float*)d_in[2];
    const float* wh   = (const float*)d_in[3];
    const float* accp = (const float*)d_in[4];
    const void*  run  = d_in[5];

    float* out      = (float*)d_out;
    float* packed   = out;                              // [B,M,H]
    float* weighted = out + (size_t)NTOK * H_;          // [B,M,H]
    float* acc      = out + 2 * (size_t)NTOK * H_;      // [B,M,1]

    rank_kernel<<<B_, 256>>>(run);

    cudaLaunchAttribute attr[1];
    attr[0].id = cudaLaunchAttributeProgrammaticStreamSerialization;
    attr[0].val.programmaticStreamSerializationAllowed = 1;

    cudaLaunchConfig_t cfg = {};
    cfg.gridDim = dim3(GROUPS * 1024);
    cfg.blockDim = dim3(128);
    cfg.dynamicSmemBytes = 0;
    cfg.stream = 0;
    cfg.attrs = attr;
    cfg.numAttrs = 1;
    cudaLaunchKernelEx(&cfg, fused_kernel, h, W, bias, wh, accp,
                       packed, weighted, acc);
}

// round 15
// speedup vs baseline: 1.3609x; 1.0274x over previous
#include <cuda_runtime.h>

#define B_ 32
#define M_ 2048
#define H_ 1024
#define NTOK (B_*M_)
#define THRESH 0.99f
#define BLOCKS_PER_BATCH (M_/4)   // 4 tokens per block -> 512 blocks/batch
#define PIPE_OFF 4                // block of group g packs batch g-4
#define GROUPS (B_+PIPE_OFF)

// Scratch (no allocations allowed).
__device__ int g_rank[NTOK];          // clip(cumsum(run)-1, 0, M-1)
__device__ unsigned char g_runb[NTOK];// decoded run mask
__device__ int g_src[NTOK];           // run_new ? rank : -1
__device__ int g_gidx[NTOK];          // packed row d -> source row in h, -1 => zero row
__device__ int g_done[B_];            // per-batch completion counters
__device__ int g_ready[B_];           // per-batch "gidx compacted" flags

// ---------------------------------------------------------------------------
// K0: wire-format probe + decode + per-batch rank scan. Resets g_done/g_ready.
// Both format interpretations loaded before the probe resolves.
// ---------------------------------------------------------------------------
__global__ void rank_kernel(const void* __restrict__ run) {
    const int b = blockIdx.x;
    const int t = threadIdx.x;            // 256 threads
    const unsigned int* w = (const unsigned int*)run;

    if (t == 0) { g_done[b] = 0; g_ready[b] = 0; }

    unsigned int p0 = w[b * 512 + t];
    unsigned int p1 = w[b * 512 + 256 + t];
    const int base = t * 8;
    uint2 u8v = *(const uint2*)((const unsigned char*)run + b * M_ + base);
    int4 i0 = ((const int4*)((const int*)run + b * M_ + base))[0];
    int4 i1 = ((const int4*)((const int*)run + b * M_ + base))[1];

    int found = ((p0 | p1) & 0xFFFFFF00u) ? 1 : 0;
    const int fmt_u8 = __syncthreads_or(found);

    int v[8];
    if (fmt_u8) {
        v[0] = (u8v.x & 0x000000FFu) != 0; v[1] = (u8v.x & 0x0000FF00u) != 0;
        v[2] = (u8v.x & 0x00FF0000u) != 0; v[3] = (u8v.x & 0xFF000000u) != 0;
        v[4] = (u8v.y & 0x000000FFu) != 0; v[5] = (u8v.y & 0x0000FF00u) != 0;
        v[6] = (u8v.y & 0x00FF0000u) != 0; v[7] = (u8v.y & 0xFF000000u) != 0;
    } else {
        v[0] = i0.x != 0; v[1] = i0.y != 0; v[2] = i0.z != 0; v[3] = i0.w != 0;
        v[4] = i1.x != 0; v[5] = i1.y != 0; v[6] = i1.z != 0; v[7] = i1.w != 0;
    }
    int s = 0;
    #pragma unroll
    for (int i = 0; i < 8; i++) {
        s += v[i];
        g_runb[b * M_ + base + i] = (unsigned char)v[i];
    }

    const int lane = t & 31, warp = t >> 5;
    int x = s;
    #pragma unroll
    for (int o = 1; o < 32; o <<= 1) {
        int y = __shfl_up_sync(0xffffffffu, x, o);
        if (lane >= o) x += y;
    }
    __shared__ int wsum[8], woff[8];
    if (lane == 31) wsum[warp] = x;
    __syncthreads();
    if (t == 0) { int a = 0; for (int i = 0; i < 8; i++) { woff[i] = a; a += wsum[i]; } }
    __syncthreads();

    int c = woff[warp] + (x - s);
    #pragma unroll
    for (int i = 0; i < 8; i++) {
        c += v[i];
        int rk = c - 1;
        if (rk < 0) rk = 0;
        g_rank[b * M_ + base + i] = rk;
    }
}

// ---------------------------------------------------------------------------
// K1: fully fused main+pack, per-block pipelining.
// Grid = GROUPS x 512 blocks. Block (g, slot):
//   main phase  (g <  B_): R10-style main work for batch g, tokens slot*4..+3,
//                          + per-batch fused compaction + g_ready publish.
//   pack phase  (g >= PIPE_OFF): packs the SAME slot of batch g-PIPE_OFF.
// The pack target is 4 batches (2048 block-dispatches) behind — beyond the
// ~1330-block resident window PLUS this block's own main-phase runtime — so
// the g_ready gate never actually spins (kept as a hard correctness fence;
// main phases never wait on anything -> no deadlock). Each block interleaves
// a read-heavy phase and a write-only phase back-to-back: finest-grain R/W
// mixing at DRAM, half the block count of R14, no padding blocks.
// ---------------------------------------------------------------------------
__global__ __launch_bounds__(128) void fused_kernel(
    const float* __restrict__ h, const float* __restrict__ W,
    const float* __restrict__ bias, const float* __restrict__ wh,
    const float* __restrict__ accp,
    float* __restrict__ packed, float* __restrict__ weighted_out,
    float* __restrict__ acc_out)
{
    __shared__ float sW[H_];
    __shared__ float sWH[4 * H_];      // 4 token rows of weighted_h

    const int group = blockIdx.x >> 9;         // /512
    const int slot  = blockIdx.x & 511;
    const int warp = threadIdx.x >> 5, lane = threadIdx.x & 31;

    if (group < B_) {
        // ===================== main phase: batch = group =====================
        const int b = group;
        const int tok = b * M_ + slot * 4 + warp;

        // ---- rank-independent prefetch (overlaps rank_kernel via PDL) ----
        for (int i = threadIdx.x; i < H_ / 4; i += 128)
            ((float4*)sW)[i] = ((const float4*)W)[i];

        {   // stage this warp's wh row: 8x LDG.128 -> 8x STS.128
            const float4* whrow = (const float4*)(wh + (size_t)tok * H_);
            float4* swh = (float4*)(sWH + warp * H_);
            float4 r[8];
            #pragma unroll
            for (int i = 0; i < 8; i++) r[i] = whrow[lane + i * 32];
            #pragma unroll
            for (int i = 0; i < 8; i++) swh[lane + i * 32] = r[i];
        }
        float acc = accp[tok];
        const float bv = bias[0];

        cudaGridDependencySynchronize();   // rank_kernel outputs now visible
        __syncthreads();

        const bool running = g_runb[tok] != 0;
        const int rank = g_rank[tok];

        float4 hv[8];
        float dot = 0.0f;
        if (running) {
            const float4* hrow = (const float4*)(h + ((size_t)b * M_ + rank) * H_);
            #pragma unroll
            for (int i = 0; i < 8; i++) {
                float4 a = hrow[lane + i * 32];
                hv[i] = a;
                float4 wv = ((const float4*)sW)[lane + i * 32];
                dot += a.x * wv.x;
                dot += a.y * wv.y;
                dot += a.z * wv.z;
                dot += a.w * wv.w;
            }
        } else {
            #pragma unroll
            for (int i = 0; i < 8; i++) hv[i] = make_float4(0.f, 0.f, 0.f, 0.f);
        }
        #pragma unroll
        for (int o = 16; o > 0; o >>= 1)
            dot += __shfl_xor_sync(0xffffffffu, dot, o);

        float p_adj = 0.0f;
        bool run_new = false;
        if (running) {
            float z = dot + bv;
            float p = 1.0f / (1.0f + expf(-z));
            float acc_new = acc + p;
            run_new = acc_new < THRESH;
            p_adj = run_new ? p : (1.0f - (acc_new - p));
            acc = acc_new;
        }
        if (lane == 0) {
            acc_out[tok] = acc;
            g_src[tok] = run_new ? rank : -1;
        }

        float4* wo = (float4*)(weighted_out + (size_t)tok * H_);
        const float4* swh = (const float4*)(sWH + warp * H_);
        const float q = 1.0f - p_adj;
        #pragma unroll
        for (int i = 0; i < 8; i++) {
            float4 w4 = swh[lane + i * 32];
            float4 o4;
            o4.x = hv[i].x * p_adj + w4.x * q;
            o4.y = hv[i].y * p_adj + w4.y * q;
            o4.z = hv[i].z * p_adj + w4.z * q;
            o4.w = hv[i].w * p_adj + w4.w * q;
            wo[lane + i * 32] = o4;
        }

        // ---- fused per-batch compaction: last-arriving block does it ----
        __shared__ int s_last;
        __syncthreads();                 // all warps' g_src writes issued
        if (threadIdx.x == 0) {
            __threadfence();             // release g_src to other SMs
            int n = atomicAdd(&g_done[b], 1);
            s_last = (n == BLOCKS_PER_BATCH - 1);
        }
        __syncthreads();
        if (s_last) {
            const int t = threadIdx.x;
            const int base = b * M_ + t * 16;
            int src[16], v[16];
            int s = 0;
            #pragma unroll
            for (int i = 0; i < 16; i++) {
                src[i] = g_src[base + i];
                v[i] = (src[i] >= 0) ? 1 : 0;
                s += v[i];
                g_gidx[base + i] = -1;       // default: zero row
            }
            int x = s;
            #pragma unroll
            for (int o = 1; o < 32; o <<= 1) {
                int y = __shfl_up_sync(0xffffffffu, x, o);
                if (lane >= o) x += y;
            }
            __shared__ int cw[4], co[4];
            if (lane == 31) cw[warp] = x;
            __syncthreads();
            if (t == 0) { int a = 0; for (int i = 0; i < 4; i++) { co[i] = a; a += cw[i]; } }
            __syncthreads();                 // orders the -1 init before scatter

            int pos = co[warp] + (x - s);
            #pragma unroll
            for (int i = 0; i < 16; i++) {
                if (v[i]) {
                    g_gidx[b * M_ + pos] = src[i];
                    pos++;
                }
            }
            if (t == 0) {
                __threadfence();             // release g_gidx
                *(volatile int*)&g_ready[b] = 1;
            }
        }
    } else {
        // pack-only trailing groups still need rank's g_ready reset ordering
        cudaGridDependencySynchronize();
    }

    // ===================== pack phase: batch = group - PIPE_OFF =============
    if (group < PIPE_OFF) return;
    const int pb = group - PIPE_OFF;
    const int ptok = pb * M_ + slot * 4 + warp;

    if (threadIdx.x == 0) {
        while (*(volatile int*)&g_ready[pb] == 0) __nanosleep(128);
        __threadfence();               // acquire: order g_gidx reads after flag
    }
    __syncthreads();

    const int g = g_gidx[ptok];
    float4* out = (float4*)(packed + (size_t)ptok * H_);
    if (g >= 0) {
        const float4* hrow = (const float4*)(h + ((size_t)pb * M_ + g) * H_);
        float4 r[8];
        #pragma unroll
        for (int i = 0; i < 8; i++) r[i] = hrow[lane + i * 32];   // L2-recent
        #pragma unroll
        for (int i = 0; i < 8; i++) out[lane + i * 32] = r[i];
    } else {
        const float4 z = make_float4(0.f, 0.f, 0.f, 0.f);
        #pragma unroll
        for (int i = 0; i < 8; i++) out[lane + i * 32] = z;
    }
}

// ---------------------------------------------------------------------------
extern "C" void kernel_launch(void* const* d_in, const int* in_sizes, int n_in,
                              void* d_out, int out_size) {
    const float* h    = (const float*)d_in[0];
    const float* W    = (const float*)d_in[1];
    const float* bias = (const float*)d_in[2];
    const float* wh   = (const float*)d_in[3];
    const float* accp = (const float*)d_in[4];
    const void*  run  = d_in[5];

    float* out      = (float*)d_out;
    float* packed   = out;                              // [B,M,H]
    float* weighted = out + (size_t)NTOK * H_;          // [B,M,H]
    float* acc      = out + 2 * (size_t)NTOK * H_;      // [B,M,1]

    rank_kernel<<<B_, 256>>>(run);

    cudaLaunchAttribute attr[1];
    attr[0].id = cudaLaunchAttributeProgrammaticStreamSerialization;
    attr[0].val.programmaticStreamSerializationAllowed = 1;

    cudaLaunchConfig_t cfg = {};
    cfg.gridDim = dim3(GROUPS * 512);
    cfg.blockDim = dim3(128);
    cfg.dynamicSmemBytes = 0;
    cfg.stream = 0;
    cfg.attrs = attr;
    cfg.numAttrs = 1;
    cudaLaunchKernelEx(&cfg, fused_kernel, h, W, bias, wh, accp,
                       packed, weighted, acc);
}

// round 16
// speedup vs baseline: 1.3652x; 1.0032x over previous
#include <cuda_runtime.h>

#define B_ 32
#define M_ 2048
#define H_ 1024
#define NTOK (B_*M_)
#define THRESH 0.99f
#define BLOCKS_PER_BATCH (M_/4)   // 4 tokens per block -> 512 blocks/batch
#define PIPE_OFF 4                // block of group g packs batch g-4
#define GROUPS (B_+PIPE_OFF)

// Scratch (no allocations allowed).
__device__ int g_rank[NTOK];          // clip(cumsum(run)-1, 0, M-1)
__device__ unsigned char g_runb[NTOK];// decoded run mask
__device__ int g_src[NTOK];           // run_new ? rank : -1
__device__ int g_gidx[NTOK];          // packed row d -> source row in h, -1 => zero row
__device__ int g_done[B_];            // per-batch completion counters
__device__ int g_ready[B_];           // per-batch "gidx compacted" flags

// ---------------------------------------------------------------------------
// K0: wire-format probe + decode + per-batch rank scan. Resets g_done/g_ready.
// FIRST ACTION: fire the PDL trigger so the fused kernel's blocks dispatch
// immediately and run their rank-independent prefetch concurrently with this
// kernel (without the trigger, dependent dispatch waits for rank COMPLETION —
// which is why previous rounds saw no real overlap).
// ---------------------------------------------------------------------------
__global__ void rank_kernel(const void* __restrict__ run) {
    cudaTriggerProgrammaticLaunchCompletion();

    const int b = blockIdx.x;
    const int t = threadIdx.x;            // 256 threads
    const unsigned int* w = (const unsigned int*)run;

    if (t == 0) { g_done[b] = 0; g_ready[b] = 0; }

    // issue everything up front: probe words + u8 view + i32 view
    unsigned int p0 = w[b * 512 + t];
    unsigned int p1 = w[b * 512 + 256 + t];
    const int base = t * 8;
    uint2 u8v = *(const uint2*)((const unsigned char*)run + b * M_ + base);
    int4 i0 = ((const int4*)((const int*)run + b * M_ + base))[0];
    int4 i1 = ((const int4*)((const int*)run + b * M_ + base))[1];

    int found = ((p0 | p1) & 0xFFFFFF00u) ? 1 : 0;
    const int fmt_u8 = __syncthreads_or(found);

    int v[8];
    if (fmt_u8) {
        v[0] = (u8v.x & 0x000000FFu) != 0; v[1] = (u8v.x & 0x0000FF00u) != 0;
        v[2] = (u8v.x & 0x00FF0000u) != 0; v[3] = (u8v.x & 0xFF000000u) != 0;
        v[4] = (u8v.y & 0x000000FFu) != 0; v[5] = (u8v.y & 0x0000FF00u) != 0;
        v[6] = (u8v.y & 0x00FF0000u) != 0; v[7] = (u8v.y & 0xFF000000u) != 0;
    } else {
        v[0] = i0.x != 0; v[1] = i0.y != 0; v[2] = i0.z != 0; v[3] = i0.w != 0;
        v[4] = i1.x != 0; v[5] = i1.y != 0; v[6] = i1.z != 0; v[7] = i1.w != 0;
    }
    int s = 0;
    #pragma unroll
    for (int i = 0; i < 8; i++) {
        s += v[i];
        g_runb[b * M_ + base + i] = (unsigned char)v[i];
    }

    const int lane = t & 31, warp = t >> 5;
    int x = s;
    #pragma unroll
    for (int o = 1; o < 32; o <<= 1) {
        int y = __shfl_up_sync(0xffffffffu, x, o);
        if (lane >= o) x += y;
    }
    __shared__ int wsum[8], woff[8];
    if (lane == 31) wsum[warp] = x;
    __syncthreads();
    if (t == 0) { int a = 0; for (int i = 0; i < 8; i++) { woff[i] = a; a += wsum[i]; } }
    __syncthreads();

    int c = woff[warp] + (x - s);
    #pragma unroll
    for (int i = 0; i < 8; i++) {
        c += v[i];
        int rk = c - 1;
        if (rk < 0) rk = 0;
        g_rank[b * M_ + base + i] = rk;
    }
}

// ---------------------------------------------------------------------------
// K1: fully fused main+pack, per-block pipelining (R15 structure, unchanged).
// Grid = GROUPS x 512 blocks. Block (g, slot):
//   main phase  (g <  B_): main work for batch g, tokens slot*4..+3,
//                          + per-batch fused compaction + g_ready publish.
//   pack phase  (g >= PIPE_OFF): packs the SAME slot of batch g-PIPE_OFF.
// Pack target is 4 batches (2048 dispatches) behind: beyond the resident
// window plus the block's own main-phase runtime, so the g_ready gate never
// actually spins (hard correctness fence only; main never waits -> no
// deadlock). Each block interleaves a read-heavy and a write-only phase.
// ---------------------------------------------------------------------------
__global__ __launch_bounds__(128) void fused_kernel(
    const float* __restrict__ h, const float* __restrict__ W,
    const float* __restrict__ bias, const float* __restrict__ wh,
    const float* __restrict__ accp,
    float* __restrict__ packed, float* __restrict__ weighted_out,
    float* __restrict__ acc_out)
{
    __shared__ float sW[H_];
    __shared__ float sWH[4 * H_];      // 4 token rows of weighted_h

    const int group = blockIdx.x >> 9;         // /512
    const int slot  = blockIdx.x & 511;
    const int warp = threadIdx.x >> 5, lane = threadIdx.x & 31;

    if (group < B_) {
        // ===================== main phase: batch = group =====================
        const int b = group;
        const int tok = b * M_ + slot * 4 + warp;

        // ---- rank-independent prefetch (now genuinely overlaps rank) ----
        for (int i = threadIdx.x; i < H_ / 4; i += 128)
            ((float4*)sW)[i] = ((const float4*)W)[i];

        {   // stage this warp's wh row: 8x LDG.128 -> 8x STS.128
            const float4* whrow = (const float4*)(wh + (size_t)tok * H_);
            float4* swh = (float4*)(sWH + warp * H_);
            float4 r[8];
            #pragma unroll
            for (int i = 0; i < 8; i++) r[i] = whrow[lane + i * 32];
            #pragma unroll
            for (int i = 0; i < 8; i++) swh[lane + i * 32] = r[i];
        }
        float acc = accp[tok];
        const float bv = bias[0];

        cudaGridDependencySynchronize();   // rank_kernel outputs now visible
        __syncthreads();

        const bool running = g_runb[tok] != 0;
        const int rank = g_rank[tok];

        float4 hv[8];
        float dot = 0.0f;
        if (running) {
            const float4* hrow = (const float4*)(h + ((size_t)b * M_ + rank) * H_);
            #pragma unroll
            for (int i = 0; i < 8; i++) {
                float4 a = hrow[lane + i * 32];
                hv[i] = a;
                float4 wv = ((const float4*)sW)[lane + i * 32];
                dot += a.x * wv.x;
                dot += a.y * wv.y;
                dot += a.z * wv.z;
                dot += a.w * wv.w;
            }
        } else {
            #pragma unroll
            for (int i = 0; i < 8; i++) hv[i] = make_float4(0.f, 0.f, 0.f, 0.f);
        }
        #pragma unroll
        for (int o = 16; o > 0; o >>= 1)
            dot += __shfl_xor_sync(0xffffffffu, dot, o);

        float p_adj = 0.0f;
        bool run_new = false;
        if (running) {
            float z = dot + bv;
            float p = 1.0f / (1.0f + expf(-z));
            float acc_new = acc + p;
            run_new = acc_new < THRESH;
            p_adj = run_new ? p : (1.0f - (acc_new - p));
            acc = acc_new;
        }
        if (lane == 0) {
            acc_out[tok] = acc;
            g_src[tok] = run_new ? rank : -1;
        }

        float4* wo = (float4*)(weighted_out + (size_t)tok * H_);
        const float4* swh = (const float4*)(sWH + warp * H_);
        const float q = 1.0f - p_adj;
        #pragma unroll
        for (int i = 0; i < 8; i++) {
            float4 w4 = swh[lane + i * 32];
            float4 o4;
            o4.x = hv[i].x * p_adj + w4.x * q;
            o4.y = hv[i].y * p_adj + w4.y * q;
            o4.z = hv[i].z * p_adj + w4.z * q;
            o4.w = hv[i].w * p_adj + w4.w * q;
            wo[lane + i * 32] = o4;
        }

        // ---- fused per-batch compaction: last-arriving block does it ----
        __shared__ int s_last;
        __syncthreads();                 // all warps' g_src writes issued
        if (threadIdx.x == 0) {
            __threadfence();             // release g_src to other SMs
            int n = atomicAdd(&g_done[b], 1);
            s_last = (n == BLOCKS_PER_BATCH - 1);
        }
        __syncthreads();
        if (s_last) {
            const int t = threadIdx.x;
            const int base = b * M_ + t * 16;
            int src[16], v[16];
            int s = 0;
            #pragma unroll
            for (int i = 0; i < 16; i++) {
                src[i] = g_src[base + i];
                v[i] = (src[i] >= 0) ? 1 : 0;
                s += v[i];
                g_gidx[base + i] = -1;       // default: zero row
            }
            int x = s;
            #pragma unroll
            for (int o = 1; o < 32; o <<= 1) {
                int y = __shfl_up_sync(0xffffffffu, x, o);
                if (lane >= o) x += y;
            }
            __shared__ int cw[4], co[4];
            if (lane == 31) cw[warp] = x;
            __syncthreads();
            if (t == 0) { int a = 0; for (int i = 0; i < 4; i++) { co[i] = a; a += cw[i]; } }
            __syncthreads();                 // orders the -1 init before scatter

            int pos = co[warp] + (x - s);
            #pragma unroll
            for (int i = 0; i < 16; i++) {
                if (v[i]) {
                    g_gidx[b * M_ + pos] = src[i];
                    pos++;
                }
            }
            if (t == 0) {
                __threadfence();             // release g_gidx
                *(volatile int*)&g_ready[b] = 1;
            }
        }
    } else {
        // pack-only trailing groups still need rank's g_ready reset ordering
        cudaGridDependencySynchronize();
    }

    // ===================== pack phase: batch = group - PIPE_OFF =============
    if (group < PIPE_OFF) return;
    const int pb = group - PIPE_OFF;
    const int ptok = pb * M_ + slot * 4 + warp;

    if (threadIdx.x == 0) {
        while (*(volatile int*)&g_ready[pb] == 0) __nanosleep(128);
        __threadfence();               // acquire: order g_gidx reads after flag
    }
    __syncthreads();

    const int g = g_gidx[ptok];
    float4* out = (float4*)(packed + (size_t)ptok * H_);
    if (g >= 0) {
        const float4* hrow = (const float4*)(h + ((size_t)pb * M_ + g) * H_);
        float4 r[8];
        #pragma unroll
        for (int i = 0; i < 8; i++) r[i] = hrow[lane + i * 32];   // L2-recent
        #pragma unroll
        for (int i = 0; i < 8; i++) out[lane + i * 32] = r[i];
    } else {
        const float4 z = make_float4(0.f, 0.f, 0.f, 0.f);
        #pragma unroll
        for (int i = 0; i < 8; i++) out[lane + i * 32] = z;
    }
}

// ---------------------------------------------------------------------------
extern "C" void kernel_launch(void* const* d_in, const int* in_sizes, int n_in,
                              void* d_out, int out_size) {
    const float* h    = (const float*)d_in[0];
    const float* W    = (const float*)d_in[1];
    const float* bias = (const float*)d_in[2];
    const float* wh   = (const float*)d_in[3];
    const float* accp = (const float*)d_in[4];
    const void*  run  = d_in[5];

    float* out      = (float*)d_out;
    float* packed   = out;                              // [B,M,H]
    float* weighted = out + (size_t)NTOK * H_;          // [B,M,H]
    float* acc      = out + 2 * (size_t)NTOK * H_;      // [B,M,1]

    rank_kernel<<<B_, 256>>>(run);

    cudaLaunchAttribute attr[1];
    attr[0].id = cudaLaunchAttributeProgrammaticStreamSerialization;
    attr[0].val.programmaticStreamSerializationAllowed = 1;

    cudaLaunchConfig_t cfg = {};
    cfg.gridDim = dim3(GROUPS * 512);
    cfg.blockDim = dim3(128);
    cfg.dynamicSmemBytes = 0;
    cfg.stream = 0;
    cfg.attrs = attr;
    cfg.numAttrs = 1;
    cudaLaunchKernelEx(&cfg, fused_kernel, h, W, bias, wh, accp,
                       packed, weighted, acc);
}